// round 13
// baseline (speedup 1.0000x reference)
#include <cuda_runtime.h>
#include <cuda_bf16.h>
#include <cstdint>

#define EPS 1e-5f
typedef unsigned long long u64;
typedef unsigned int u32;
typedef unsigned short u16;

// ---------------- device scratch ----------------
__device__ float g_a2[64], g_b2[64];
__device__ float g_a3[2048], g_b3[2048];
__device__ u64 g_w2bits[64 * 9];
__device__ u64 g_fc1bits[2048 * 49];
__device__ u64 g_fc2bits[10 * 32];
__device__ u64 g_bits1[2048 * 14 * 14];
__device__ u64 g_bits2[2048 * 7 * 7];
__device__ u64 g_bits3[2048 * 32];

// ---------------- packed f32x2 helpers ----------------
__device__ __forceinline__ u64 fma2(u64 a, u64 b, u64 c) {
    u64 d;
    asm("fma.rn.f32x2 %0, %1, %2, %3;" : "=l"(d) : "l"(a), "l"(b), "l"(c));
    return d;
}
__device__ __forceinline__ u64 pack2(float lo, float hi) {
    u64 d;
    asm("mov.b64 %0, {%1, %2};" : "=l"(d) : "f"(lo), "f"(hi));
    return d;
}
__device__ __forceinline__ void unpack2(u64 v, float& lo, float& hi) {
    asm("mov.b64 {%0, %1}, %2;" : "=f"(lo), "=f"(hi) : "l"(v));
}

// ================= kA: conv1 full + heavy weight prep (role by blockIdx) =================
#define NB_CONV1 1568
#define NB_FC1W  2048
#define NB_W2    64
#define NB_KA (NB_CONV1 + NB_FC1W + NB_W2)

__global__ __launch_bounds__(256, 4) void kA(
    const float* __restrict__ x, const float* __restrict__ w1,
    const float* __restrict__ g1, const float* __restrict__ be1,
    const float* __restrict__ m1, const float* __restrict__ v1,
    const float* __restrict__ w2,
    const float* __restrict__ wfc1)
{
    __shared__ u64 sw[576];
    __shared__ float sa[64], sb[64];
    __shared__ u32 sbits[98];
    __shared__ u32 sp[98];

    int bid = blockIdx.x;
    int tid = threadIdx.x;

    if (bid < NB_CONV1) {
        // ---- conv1 role (known-good) ----
        for (int i = tid; i < 576; i += 256) {
            float s = (w1[i] >= 0.0f) ? 1.0f : -1.0f;
            sw[i] = pack2(s, s);
        }
        if (tid < 64) {
            float a = g1[tid] / sqrtf(v1[tid] + EPS);
            sa[tid] = a;
            sb[tid] = be1[tid] - m1[tid] * a;
        }
        __syncthreads();

        int idx = bid * 256 + tid;
        int b = idx / 196, p = idx % 196;
        int py = p / 14, px = p % 14;
        const float* xb = x + b * 784;

        u64 pr[4][3];
#pragma unroll
        for (int r = 0; r < 4; r++) {
            int rr = 2 * py - 1 + r; rr = min(max(rr, 0), 27);
            const float* xr = xb + rr * 28;
            int c0 = max(2 * px - 1, 0);
            int c3 = min(2 * px + 2, 27);
            float f0 = xr[c0];
            float f1 = xr[2 * px];
            float f2 = xr[2 * px + 1];
            float f3 = xr[c3];
            pr[r][0] = pack2(f0, f1);
            pr[r][1] = pack2(f1, f2);
            pr[r][2] = pack2(f2, f3);
        }

        u64 word = 0ULL;
        for (int co = 0; co < 64; co += 2) {
            u64 a00 = 0ULL, a01 = 0ULL, a10 = 0ULL, a11 = 0ULL;
            const u64* w0 = &sw[co * 9];
#pragma unroll
            for (int ky = 0; ky < 3; ky++)
#pragma unroll
                for (int kx = 0; kx < 3; kx++) {
                    u64 wa = w0[ky * 3 + kx], wb = w0[9 + ky * 3 + kx];
                    a00 = fma2(wa, pr[ky][kx], a00);
                    a01 = fma2(wa, pr[ky + 1][kx], a01);
                    a10 = fma2(wb, pr[ky][kx], a10);
                    a11 = fma2(wb, pr[ky + 1][kx], a11);
                }
            float v0, v1x, v2, v3;
            unpack2(a00, v0, v1x); unpack2(a01, v2, v3);
            float m0 = fmaxf(fmaxf(v0, v1x), fmaxf(v2, v3));
            unpack2(a10, v0, v1x); unpack2(a11, v2, v3);
            float m1v = fmaxf(fmaxf(v0, v1x), fmaxf(v2, v3));
            if (fmaf(sa[co], m0, sb[co]) >= 0.0f)          word |= 1ULL << co;
            if (fmaf(sa[co + 1], m1v, sb[co + 1]) >= 0.0f) word |= 1ULL << (co + 1);
        }
        g_bits1[b * 196 + p] = word;

    } else if (bid < NB_CONV1 + NB_FC1W) {
        // ---- fc1 weight pack role ----
        int o = bid - NB_CONV1;
        const float* wo = wfc1 + (long long)o * 3136;
#pragma unroll
        for (int it = 0; it < 13; it++) {
            int i = it * 256 + tid;
            bool v = (i < 3136) ? (wo[i] >= 0.0f) : false;
            u32 m = __ballot_sync(0xffffffffu, v);
            if ((tid & 31) == 0 && i < 3136) sbits[i >> 5] = m;
        }
        __syncthreads();
        if (tid < 98) {
            int j = tid % 49, half = tid / 49;
            u32 part = 0;
#pragma unroll
            for (int cc = 0; cc < 32; cc++) {
                int c = half * 32 + cc;
                int fi = c * 49 + j;
                part |= ((sbits[fi >> 5] >> (fi & 31)) & 1u) << cc;
            }
            sp[tid] = part;
        }
        __syncthreads();
        if (tid < 49)
            g_fc1bits[o * 49 + tid] = (u64)sp[tid] | ((u64)sp[tid + 49] << 32);

    } else {
        // ---- conv2 weight pack role ----
        int co = bid - NB_CONV1 - NB_FC1W;
        const float* wc = w2 + co * 576;
#pragma unroll
        for (int it = 0; it < 3; it++) {
            int i = it * 256 + tid;
            bool v = (i < 576) ? (wc[i] >= 0.0f) : false;
            u32 m = __ballot_sync(0xffffffffu, v);
            if ((tid & 31) == 0 && i < 576) sbits[i >> 5] = m;
        }
        __syncthreads();
        if (tid < 9) {
            u64 word = 0ULL;
#pragma unroll
            for (int cin = 0; cin < 64; cin++) {
                int fi = cin * 9 + tid;
                word |= (u64)((sbits[fi >> 5] >> (fi & 31)) & 1u) << cin;
            }
            g_w2bits[co * 9 + tid] = word;
        }
    }
}

// ================= tiny #2: bn folds =================
__global__ void k_bn(const float* __restrict__ g2, const float* __restrict__ be2,
                     const float* __restrict__ m2, const float* __restrict__ v2,
                     const float* __restrict__ g3, const float* __restrict__ be3,
                     const float* __restrict__ m3, const float* __restrict__ v3) {
    int i = blockIdx.x * 256 + threadIdx.x;
    if (i < 2048) {
        float a = g3[i] / sqrtf(v3[i] + EPS);
        g_a3[i] = a;
        g_b3[i] = be3[i] - m3[i] * a;
    }
    if (i < 64) {
        float a = g2[i] / sqrtf(v2[i] + EPS);
        g_a2[i] = a;
        g_b2[i] = be2[i] - m2[i] * a;
    }
}

// ================= tiny #3: fc2 weight pack =================
__global__ void k_fc2w(const float* __restrict__ wfc2) {
    __shared__ u32 sbits[64];
    int o = blockIdx.x;
    int tid = threadIdx.x;
    const float* wo = wfc2 + o * 2048;
#pragma unroll
    for (int it = 0; it < 8; it++) {
        int i = it * 256 + tid;
        u32 m = __ballot_sync(0xffffffffu, wo[i] >= 0.0f);
        if ((tid & 31) == 0) sbits[i >> 5] = m;
    }
    __syncthreads();
    if (tid < 32)
        g_fc2bits[o * 32 + tid] = (u64)sbits[2 * tid] | ((u64)sbits[2 * tid + 1] << 32);
}

// ================= conv2: 4-way channel-split, WARP-UNIFORM channel group =================
// warp = idx>>5; cg = warp & 3 (uniform across lanes -> weight LDS broadcast);
// pixel pp = (warp>>2)*32 + lane (coalesced pixel loads).
// u16 planes alias the u64 channel word exactly (little endian): no atomics.
__global__ __launch_bounds__(256) void conv2_kernel() {
    __shared__ __align__(16) u64 sw[640];   // stride 10 per co (80B, 16B-aligned)
    __shared__ float sa[64], sb[64];
    int tid = threadIdx.x;
    for (int i = tid; i < 576; i += 256) {
        int co = i / 9, q = i - co * 9;
        sw[co * 10 + q] = g_w2bits[i];
    }
    if (tid < 64) { sa[tid] = g_a2[tid]; sb[tid] = g_b2[tid]; }
    __syncthreads();

    int gw = (blockIdx.x * 256 + tid) >> 5;  // global warp id [0, 12544)
    int lane = tid & 31;
    int cg = gw & 3;                          // uniform within warp
    int pp = (gw >> 2) * 32 + lane;           // [0, 2048*49)
    int b = pp / 49, p = pp % 49;
    int py = p / 7, px = p % 7;
    const u64* ib = g_bits1 + b * 196;

    u64 pix[16];
#pragma unroll
    for (int i = 0; i < 4; i++) {
        int r = 2 * py - 1 + i; r = min(max(r, 0), 13);
#pragma unroll
        for (int j = 0; j < 4; j++) {
            int c = 2 * px - 1 + j; c = min(max(c, 0), 13);
            pix[i * 4 + j] = ib[r * 14 + c];
        }
    }

    u32 bits16 = 0;
    int co0 = cg * 16;
    for (int t = 0; t < 16; t++) {
        const u64* wp = &sw[(co0 + t) * 10];
        u64 wreg[9];
#pragma unroll
        for (int q = 0; q < 9; q++) wreg[q] = wp[q];
        int smin = 1 << 30;
#pragma unroll
        for (int dy = 0; dy < 2; dy++)
#pragma unroll
            for (int dx = 0; dx < 2; dx++) {
                int s = 0;
#pragma unroll
                for (int ky = 0; ky < 3; ky++)
#pragma unroll
                    for (int kx = 0; kx < 3; kx++)
                        s += __popcll(pix[(dy + ky) * 4 + (dx + kx)] ^ wreg[ky * 3 + kx]);
                smin = min(smin, s);
            }
        float d = (float)(576 - 2 * smin);
        if (fmaf(sa[co0 + t], d, sb[co0 + t]) >= 0.0f) bits16 |= 1u << t;
    }
    ((u16*)g_bits2)[pp * 4 + cg] = (u16)bits16;
}

// ================= fc1: 64x64 XNOR GEMM + bn3 + sign + pack (r9 known-good) =================
__global__ __launch_bounds__(256) void fc1_kernel() {
    __shared__ u64 sA[64][25];
    __shared__ u64 sB[64][25];
    __shared__ u64 obits[64];
    __shared__ float sa3[64], sb3[64];
    int tid = threadIdx.x;
    int tx = tid & 15, ty = tid >> 4;
    int m0 = blockIdx.y * 64;
    int n0 = blockIdx.x * 64;

    if (tid < 64) {
        obits[tid] = 0ULL;
        sa3[tid] = g_a3[n0 + tid];
        sb3[tid] = g_b3[n0 + tid];
    }

    int acc[4][4];
#pragma unroll
    for (int i = 0; i < 4; i++)
#pragma unroll
        for (int j = 0; j < 4; j++) acc[i][j] = 0;

    for (int e = tid; e < 64 * 25; e += 256) {
        int r = e / 25, kk = e % 25;
        sA[r][kk] = g_bits2[(m0 + r) * 49 + kk];
        sB[r][kk] = g_fc1bits[(n0 + r) * 49 + kk];
    }
    __syncthreads();
#pragma unroll 5
    for (int kk = 0; kk < 25; kk++) {
        u64 a0 = sA[ty][kk], a1 = sA[ty + 16][kk], a2 = sA[ty + 32][kk], a3 = sA[ty + 48][kk];
        u64 b0 = sB[tx][kk], b1 = sB[tx + 16][kk], b2 = sB[tx + 32][kk], b3 = sB[tx + 48][kk];
        acc[0][0] += __popcll(a0 ^ b0); acc[0][1] += __popcll(a0 ^ b1);
        acc[0][2] += __popcll(a0 ^ b2); acc[0][3] += __popcll(a0 ^ b3);
        acc[1][0] += __popcll(a1 ^ b0); acc[1][1] += __popcll(a1 ^ b1);
        acc[1][2] += __popcll(a1 ^ b2); acc[1][3] += __popcll(a1 ^ b3);
        acc[2][0] += __popcll(a2 ^ b0); acc[2][1] += __popcll(a2 ^ b1);
        acc[2][2] += __popcll(a2 ^ b2); acc[2][3] += __popcll(a2 ^ b3);
        acc[3][0] += __popcll(a3 ^ b0); acc[3][1] += __popcll(a3 ^ b1);
        acc[3][2] += __popcll(a3 ^ b2); acc[3][3] += __popcll(a3 ^ b3);
    }
    __syncthreads();
    for (int e = tid; e < 64 * 24; e += 256) {
        int r = e / 24, kk = e % 24;
        sA[r][kk] = g_bits2[(m0 + r) * 49 + 25 + kk];
        sB[r][kk] = g_fc1bits[(n0 + r) * 49 + 25 + kk];
    }
    __syncthreads();
#pragma unroll 4
    for (int kk = 0; kk < 24; kk++) {
        u64 a0 = sA[ty][kk], a1 = sA[ty + 16][kk], a2 = sA[ty + 32][kk], a3 = sA[ty + 48][kk];
        u64 b0 = sB[tx][kk], b1 = sB[tx + 16][kk], b2 = sB[tx + 32][kk], b3 = sB[tx + 48][kk];
        acc[0][0] += __popcll(a0 ^ b0); acc[0][1] += __popcll(a0 ^ b1);
        acc[0][2] += __popcll(a0 ^ b2); acc[0][3] += __popcll(a0 ^ b3);
        acc[1][0] += __popcll(a1 ^ b0); acc[1][1] += __popcll(a1 ^ b1);
        acc[1][2] += __popcll(a1 ^ b2); acc[1][3] += __popcll(a1 ^ b3);
        acc[2][0] += __popcll(a2 ^ b0); acc[2][1] += __popcll(a2 ^ b1);
        acc[2][2] += __popcll(a2 ^ b2); acc[2][3] += __popcll(a2 ^ b3);
        acc[3][0] += __popcll(a3 ^ b0); acc[3][1] += __popcll(a3 ^ b1);
        acc[3][2] += __popcll(a3 ^ b2); acc[3][3] += __popcll(a3 ^ b3);
    }

#pragma unroll
    for (int i = 0; i < 4; i++) {
        u64 bits = 0ULL;
#pragma unroll
        for (int j = 0; j < 4; j++) {
            int c = tx + 16 * j;
            float d = (float)(3136 - 2 * acc[i][j]);
            if (fmaf(sa3[c], d, sb3[c]) >= 0.0f) bits |= 1ULL << c;
        }
        atomicOr(&obits[ty + 16 * i], bits);
    }
    __syncthreads();
    if (tid < 64)
        g_bits3[(m0 + tid) * 32 + blockIdx.x] = obits[tid];
}

// ================= fc2: warp-per-row XNOR + scale (known-good) =================
__global__ __launch_bounds__(256) void fc2_kernel(float* __restrict__ out,
                                                  const float* __restrict__ scale) {
    __shared__ u64 sw[10][32];
    int tid = threadIdx.x;
    for (int i = tid; i < 320; i += 256)
        ((u64*)sw)[i] = g_fc2bits[i];
    __syncthreads();

    int warp = tid >> 5, lane = tid & 31;
    int b = blockIdx.x * 8 + warp;
    u64 xw = g_bits3[b * 32 + lane];
    float sc = scale[0];
#pragma unroll
    for (int o = 0; o < 10; o++) {
        u32 p = (u32)__popcll(xw ^ sw[o][lane]);
        u32 s = __reduce_add_sync(0xffffffffu, p);
        if (lane == o)
            out[b * 10 + o] = sc * (float)(2048 - 2 * (int)s);
    }
}

// ================= launch =================
extern "C" void kernel_launch(void* const* d_in, const int* in_sizes, int n_in,
                              void* d_out, int out_size) {
    const float* x       = (const float*)d_in[0];
    const float* conv1_w = (const float*)d_in[1];
    const float* bn1_g   = (const float*)d_in[2];
    const float* bn1_b   = (const float*)d_in[3];
    const float* bn1_m   = (const float*)d_in[4];
    const float* bn1_v   = (const float*)d_in[5];
    const float* conv2_w = (const float*)d_in[6];
    const float* bn2_g   = (const float*)d_in[7];
    const float* bn2_b   = (const float*)d_in[8];
    const float* bn2_m   = (const float*)d_in[9];
    const float* bn2_v   = (const float*)d_in[10];
    const float* fc1_w   = (const float*)d_in[11];
    const float* bn3_g   = (const float*)d_in[12];
    const float* bn3_b   = (const float*)d_in[13];
    const float* bn3_m   = (const float*)d_in[14];
    const float* bn3_v   = (const float*)d_in[15];
    const float* fc2_w   = (const float*)d_in[16];
    const float* scale   = (const float*)d_in[17];
    float* out = (float*)d_out;

    // launch order: conv2 is #4 (profiler slot)
    kA<<<NB_KA, 256>>>(x, conv1_w, bn1_g, bn1_b, bn1_m, bn1_v, conv2_w, fc1_w);
    k_bn<<<8, 256>>>(bn2_g, bn2_b, bn2_m, bn2_v, bn3_g, bn3_b, bn3_m, bn3_v);
    k_fc2w<<<10, 256>>>(fc2_w);
    conv2_kernel<<<1568, 256>>>();          // 2048*49*4 threads, warp-uniform cg
    fc1_kernel<<<dim3(32, 32), 256>>>();
    fc2_kernel<<<256, 256>>>(out, scale);
}

// round 14
// speedup vs baseline: 1.0166x; 1.0166x over previous
#include <cuda_runtime.h>
#include <cuda_bf16.h>
#include <cstdint>

#define EPS 1e-5f
typedef unsigned long long u64;
typedef unsigned int u32;
typedef unsigned short u16;

// ---------------- device scratch ----------------
__device__ float g_a2[64], g_b2[64];
__device__ float g_a3[2048], g_b3[2048];
__device__ u64 g_w2bits[64 * 9];
__device__ u64 g_fc1bits[2048 * 49];
__device__ u64 g_fc2bits[10 * 32];
__device__ u64 g_bits1[2048 * 14 * 14];
__device__ u64 g_bits2[2048 * 7 * 7];
__device__ u64 g_bits3[2048 * 32];

// ---------------- packed f32x2 helpers ----------------
__device__ __forceinline__ u64 fma2(u64 a, u64 b, u64 c) {
    u64 d;
    asm("fma.rn.f32x2 %0, %1, %2, %3;" : "=l"(d) : "l"(a), "l"(b), "l"(c));
    return d;
}
__device__ __forceinline__ u64 pack2(float lo, float hi) {
    u64 d;
    asm("mov.b64 %0, {%1, %2};" : "=l"(d) : "f"(lo), "f"(hi));
    return d;
}
__device__ __forceinline__ void unpack2(u64 v, float& lo, float& hi) {
    asm("mov.b64 {%0, %1}, %2;" : "=f"(lo), "=f"(hi) : "l"(v));
}

// ================= kA: conv1 full + heavy weight prep (role by blockIdx) =================
#define NB_CONV1 1568
#define NB_FC1W  2048
#define NB_W2    64
#define NB_KA (NB_CONV1 + NB_FC1W + NB_W2)

__global__ __launch_bounds__(256, 4) void kA(
    const float* __restrict__ x, const float* __restrict__ w1,
    const float* __restrict__ g1, const float* __restrict__ be1,
    const float* __restrict__ m1, const float* __restrict__ v1,
    const float* __restrict__ w2,
    const float* __restrict__ wfc1)
{
    __shared__ u64 sw[576];
    __shared__ float sa[64], sb[64];
    __shared__ u32 sbits[98];
    __shared__ u32 sp[98];

    int bid = blockIdx.x;
    int tid = threadIdx.x;

    if (bid < NB_CONV1) {
        // ---- conv1 role (known-good) ----
        for (int i = tid; i < 576; i += 256) {
            float s = (w1[i] >= 0.0f) ? 1.0f : -1.0f;
            sw[i] = pack2(s, s);
        }
        if (tid < 64) {
            float a = g1[tid] / sqrtf(v1[tid] + EPS);
            sa[tid] = a;
            sb[tid] = be1[tid] - m1[tid] * a;
        }
        __syncthreads();

        int idx = bid * 256 + tid;
        int b = idx / 196, p = idx % 196;
        int py = p / 14, px = p % 14;
        const float* xb = x + b * 784;

        u64 pr[4][3];
#pragma unroll
        for (int r = 0; r < 4; r++) {
            int rr = 2 * py - 1 + r; rr = min(max(rr, 0), 27);
            const float* xr = xb + rr * 28;
            int c0 = max(2 * px - 1, 0);
            int c3 = min(2 * px + 2, 27);
            float f0 = xr[c0];
            float f1 = xr[2 * px];
            float f2 = xr[2 * px + 1];
            float f3 = xr[c3];
            pr[r][0] = pack2(f0, f1);
            pr[r][1] = pack2(f1, f2);
            pr[r][2] = pack2(f2, f3);
        }

        u64 word = 0ULL;
        for (int co = 0; co < 64; co += 2) {
            u64 a00 = 0ULL, a01 = 0ULL, a10 = 0ULL, a11 = 0ULL;
            const u64* w0 = &sw[co * 9];
#pragma unroll
            for (int ky = 0; ky < 3; ky++)
#pragma unroll
                for (int kx = 0; kx < 3; kx++) {
                    u64 wa = w0[ky * 3 + kx], wb = w0[9 + ky * 3 + kx];
                    a00 = fma2(wa, pr[ky][kx], a00);
                    a01 = fma2(wa, pr[ky + 1][kx], a01);
                    a10 = fma2(wb, pr[ky][kx], a10);
                    a11 = fma2(wb, pr[ky + 1][kx], a11);
                }
            float v0, v1x, v2, v3;
            unpack2(a00, v0, v1x); unpack2(a01, v2, v3);
            float m0 = fmaxf(fmaxf(v0, v1x), fmaxf(v2, v3));
            unpack2(a10, v0, v1x); unpack2(a11, v2, v3);
            float m1v = fmaxf(fmaxf(v0, v1x), fmaxf(v2, v3));
            if (fmaf(sa[co], m0, sb[co]) >= 0.0f)          word |= 1ULL << co;
            if (fmaf(sa[co + 1], m1v, sb[co + 1]) >= 0.0f) word |= 1ULL << (co + 1);
        }
        g_bits1[b * 196 + p] = word;

    } else if (bid < NB_CONV1 + NB_FC1W) {
        // ---- fc1 weight pack role ----
        int o = bid - NB_CONV1;
        const float* wo = wfc1 + (long long)o * 3136;
#pragma unroll
        for (int it = 0; it < 13; it++) {
            int i = it * 256 + tid;
            bool v = (i < 3136) ? (wo[i] >= 0.0f) : false;
            u32 m = __ballot_sync(0xffffffffu, v);
            if ((tid & 31) == 0 && i < 3136) sbits[i >> 5] = m;
        }
        __syncthreads();
        if (tid < 98) {
            int j = tid % 49, half = tid / 49;
            u32 part = 0;
#pragma unroll
            for (int cc = 0; cc < 32; cc++) {
                int c = half * 32 + cc;
                int fi = c * 49 + j;
                part |= ((sbits[fi >> 5] >> (fi & 31)) & 1u) << cc;
            }
            sp[tid] = part;
        }
        __syncthreads();
        if (tid < 49)
            g_fc1bits[o * 49 + tid] = (u64)sp[tid] | ((u64)sp[tid + 49] << 32);

    } else {
        // ---- conv2 weight pack role ----
        int co = bid - NB_CONV1 - NB_FC1W;
        const float* wc = w2 + co * 576;
#pragma unroll
        for (int it = 0; it < 3; it++) {
            int i = it * 256 + tid;
            bool v = (i < 576) ? (wc[i] >= 0.0f) : false;
            u32 m = __ballot_sync(0xffffffffu, v);
            if ((tid & 31) == 0 && i < 576) sbits[i >> 5] = m;
        }
        __syncthreads();
        if (tid < 9) {
            u64 word = 0ULL;
#pragma unroll
            for (int cin = 0; cin < 64; cin++) {
                int fi = cin * 9 + tid;
                word |= (u64)((sbits[fi >> 5] >> (fi & 31)) & 1u) << cin;
            }
            g_w2bits[co * 9 + tid] = word;
        }
    }
}

// ================= tiny #2: bn folds =================
__global__ void k_bn(const float* __restrict__ g2, const float* __restrict__ be2,
                     const float* __restrict__ m2, const float* __restrict__ v2,
                     const float* __restrict__ g3, const float* __restrict__ be3,
                     const float* __restrict__ m3, const float* __restrict__ v3) {
    int i = blockIdx.x * 256 + threadIdx.x;
    if (i < 2048) {
        float a = g3[i] / sqrtf(v3[i] + EPS);
        g_a3[i] = a;
        g_b3[i] = be3[i] - m3[i] * a;
    }
    if (i < 64) {
        float a = g2[i] / sqrtf(v2[i] + EPS);
        g_a2[i] = a;
        g_b2[i] = be2[i] - m2[i] * a;
    }
}

// ================= tiny #3: fc2 weight pack =================
__global__ void k_fc2w(const float* __restrict__ wfc2) {
    __shared__ u32 sbits[64];
    int o = blockIdx.x;
    int tid = threadIdx.x;
    const float* wo = wfc2 + o * 2048;
#pragma unroll
    for (int it = 0; it < 8; it++) {
        int i = it * 256 + tid;
        u32 m = __ballot_sync(0xffffffffu, wo[i] >= 0.0f);
        if ((tid & 31) == 0) sbits[i >> 5] = m;
    }
    __syncthreads();
    if (tid < 32)
        g_fc2bits[o * 32 + tid] = (u64)sbits[2 * tid] | ((u64)sbits[2 * tid + 1] << 32);
}

// ================= conv2: window-split across lanes =================
// lane = octet*4 + subpos; each lane computes ONE conv sub-position (9 taps) for
// 16 output channels; smin min-reduced over the 4 subpos lanes via shfl.bfly.
// cg = warp & 3 (warp-uniform weight broadcast). u16 planes alias u64 words.
__global__ __launch_bounds__(256) void conv2_kernel() {
    __shared__ __align__(16) u64 sw[640];   // stride 10 per co
    __shared__ float sa[64], sb[64];
    int tid = threadIdx.x;
    for (int i = tid; i < 576; i += 256) {
        int co = i / 9, q = i - co * 9;
        sw[co * 10 + q] = g_w2bits[i];
    }
    if (tid < 64) { sa[tid] = g_a2[tid]; sb[tid] = g_b2[tid]; }
    __syncthreads();

    int gw = (blockIdx.x * 256 + tid) >> 5;  // global warp id [0, 50176)
    int lane = tid & 31;
    int cg = gw & 3;                          // uniform within warp
    int oct = gw >> 2;                        // pooled-pixel octet [0, 12544)
    int o8 = lane >> 2;                       // pooled pixel within octet
    int sp = lane & 3;                        // sub-position: dy = sp>>1, dx = sp&1
    int pp = oct * 8 + o8;                    // [0, 2048*49)
    int b = pp / 49, p = pp % 49;
    int py = p / 7, px = p % 7;
    int dy = sp >> 1, dx = sp & 1;
    const u64* ib = g_bits1 + b * 196;

    // this lane's 3x3 window at sub-position (dy,dx)
    u64 pix[9];
#pragma unroll
    for (int ky = 0; ky < 3; ky++) {
        int r = 2 * py - 1 + dy + ky; r = min(max(r, 0), 13);
#pragma unroll
        for (int kx = 0; kx < 3; kx++) {
            int c = 2 * px - 1 + dx + kx; c = min(max(c, 0), 13);
            pix[ky * 3 + kx] = ib[r * 14 + c];
        }
    }

    u32 bits16 = 0;
    int co0 = cg * 16;
#pragma unroll 4
    for (int t = 0; t < 16; t++) {
        const u64* wp = &sw[(co0 + t) * 10];
        int s = 0;
#pragma unroll
        for (int q = 0; q < 9; q++)
            s += __popcll(pix[q] ^ wp[q]);
        // min over the 4 sub-position lanes (dot = 576-2s; a>=0 -> pooled sign from min s)
        s = min(s, __shfl_xor_sync(0xffffffffu, s, 1));
        s = min(s, __shfl_xor_sync(0xffffffffu, s, 2));
        float d = (float)(576 - 2 * s);
        if (fmaf(sa[co0 + t], d, sb[co0 + t]) >= 0.0f) bits16 |= 1u << t;
    }
    if (sp == 0)
        ((u16*)g_bits2)[pp * 4 + cg] = (u16)bits16;
}

// ================= fc1: 64x64 XNOR GEMM + bn3 + sign + pack (known-good) =================
__global__ __launch_bounds__(256) void fc1_kernel() {
    __shared__ u64 sA[64][25];
    __shared__ u64 sB[64][25];
    __shared__ u64 obits[64];
    __shared__ float sa3[64], sb3[64];
    int tid = threadIdx.x;
    int tx = tid & 15, ty = tid >> 4;
    int m0 = blockIdx.y * 64;
    int n0 = blockIdx.x * 64;

    if (tid < 64) {
        obits[tid] = 0ULL;
        sa3[tid] = g_a3[n0 + tid];
        sb3[tid] = g_b3[n0 + tid];
    }

    int acc[4][4];
#pragma unroll
    for (int i = 0; i < 4; i++)
#pragma unroll
        for (int j = 0; j < 4; j++) acc[i][j] = 0;

    for (int e = tid; e < 64 * 25; e += 256) {
        int r = e / 25, kk = e % 25;
        sA[r][kk] = g_bits2[(m0 + r) * 49 + kk];
        sB[r][kk] = g_fc1bits[(n0 + r) * 49 + kk];
    }
    __syncthreads();
#pragma unroll 5
    for (int kk = 0; kk < 25; kk++) {
        u64 a0 = sA[ty][kk], a1 = sA[ty + 16][kk], a2 = sA[ty + 32][kk], a3 = sA[ty + 48][kk];
        u64 b0 = sB[tx][kk], b1 = sB[tx + 16][kk], b2 = sB[tx + 32][kk], b3 = sB[tx + 48][kk];
        acc[0][0] += __popcll(a0 ^ b0); acc[0][1] += __popcll(a0 ^ b1);
        acc[0][2] += __popcll(a0 ^ b2); acc[0][3] += __popcll(a0 ^ b3);
        acc[1][0] += __popcll(a1 ^ b0); acc[1][1] += __popcll(a1 ^ b1);
        acc[1][2] += __popcll(a1 ^ b2); acc[1][3] += __popcll(a1 ^ b3);
        acc[2][0] += __popcll(a2 ^ b0); acc[2][1] += __popcll(a2 ^ b1);
        acc[2][2] += __popcll(a2 ^ b2); acc[2][3] += __popcll(a2 ^ b3);
        acc[3][0] += __popcll(a3 ^ b0); acc[3][1] += __popcll(a3 ^ b1);
        acc[3][2] += __popcll(a3 ^ b2); acc[3][3] += __popcll(a3 ^ b3);
    }
    __syncthreads();
    for (int e = tid; e < 64 * 24; e += 256) {
        int r = e / 24, kk = e % 24;
        sA[r][kk] = g_bits2[(m0 + r) * 49 + 25 + kk];
        sB[r][kk] = g_fc1bits[(n0 + r) * 49 + 25 + kk];
    }
    __syncthreads();
#pragma unroll 4
    for (int kk = 0; kk < 24; kk++) {
        u64 a0 = sA[ty][kk], a1 = sA[ty + 16][kk], a2 = sA[ty + 32][kk], a3 = sA[ty + 48][kk];
        u64 b0 = sB[tx][kk], b1 = sB[tx + 16][kk], b2 = sB[tx + 32][kk], b3 = sB[tx + 48][kk];
        acc[0][0] += __popcll(a0 ^ b0); acc[0][1] += __popcll(a0 ^ b1);
        acc[0][2] += __popcll(a0 ^ b2); acc[0][3] += __popcll(a0 ^ b3);
        acc[1][0] += __popcll(a1 ^ b0); acc[1][1] += __popcll(a1 ^ b1);
        acc[1][2] += __popcll(a1 ^ b2); acc[1][3] += __popcll(a1 ^ b3);
        acc[2][0] += __popcll(a2 ^ b0); acc[2][1] += __popcll(a2 ^ b1);
        acc[2][2] += __popcll(a2 ^ b2); acc[2][3] += __popcll(a2 ^ b3);
        acc[3][0] += __popcll(a3 ^ b0); acc[3][1] += __popcll(a3 ^ b1);
        acc[3][2] += __popcll(a3 ^ b2); acc[3][3] += __popcll(a3 ^ b3);
    }

#pragma unroll
    for (int i = 0; i < 4; i++) {
        u64 bits = 0ULL;
#pragma unroll
        for (int j = 0; j < 4; j++) {
            int c = tx + 16 * j;
            float d = (float)(3136 - 2 * acc[i][j]);
            if (fmaf(sa3[c], d, sb3[c]) >= 0.0f) bits |= 1ULL << c;
        }
        atomicOr(&obits[ty + 16 * i], bits);
    }
    __syncthreads();
    if (tid < 64)
        g_bits3[(m0 + tid) * 32 + blockIdx.x] = obits[tid];
}

// ================= fc2: warp-per-row XNOR + scale (known-good) =================
__global__ __launch_bounds__(256) void fc2_kernel(float* __restrict__ out,
                                                  const float* __restrict__ scale) {
    __shared__ u64 sw[10][32];
    int tid = threadIdx.x;
    for (int i = tid; i < 320; i += 256)
        ((u64*)sw)[i] = g_fc2bits[i];
    __syncthreads();

    int warp = tid >> 5, lane = tid & 31;
    int b = blockIdx.x * 8 + warp;
    u64 xw = g_bits3[b * 32 + lane];
    float sc = scale[0];
#pragma unroll
    for (int o = 0; o < 10; o++) {
        u32 p = (u32)__popcll(xw ^ sw[o][lane]);
        u32 s = __reduce_add_sync(0xffffffffu, p);
        if (lane == o)
            out[b * 10 + o] = sc * (float)(2048 - 2 * (int)s);
    }
}

// ================= launch =================
extern "C" void kernel_launch(void* const* d_in, const int* in_sizes, int n_in,
                              void* d_out, int out_size) {
    const float* x       = (const float*)d_in[0];
    const float* conv1_w = (const float*)d_in[1];
    const float* bn1_g   = (const float*)d_in[2];
    const float* bn1_b   = (const float*)d_in[3];
    const float* bn1_m   = (const float*)d_in[4];
    const float* bn1_v   = (const float*)d_in[5];
    const float* conv2_w = (const float*)d_in[6];
    const float* bn2_g   = (const float*)d_in[7];
    const float* bn2_b   = (const float*)d_in[8];
    const float* bn2_m   = (const float*)d_in[9];
    const float* bn2_v   = (const float*)d_in[10];
    const float* fc1_w   = (const float*)d_in[11];
    const float* bn3_g   = (const float*)d_in[12];
    const float* bn3_b   = (const float*)d_in[13];
    const float* bn3_m   = (const float*)d_in[14];
    const float* bn3_v   = (const float*)d_in[15];
    const float* fc2_w   = (const float*)d_in[16];
    const float* scale   = (const float*)d_in[17];
    float* out = (float*)d_out;

    // launch order: conv2 is #4 (profiler slot)
    kA<<<NB_KA, 256>>>(x, conv1_w, bn1_g, bn1_b, bn1_m, bn1_v, conv2_w, fc1_w);
    k_bn<<<8, 256>>>(bn2_g, bn2_b, bn2_m, bn2_v, bn3_g, bn3_b, bn3_m, bn3_v);
    k_fc2w<<<10, 256>>>(fc2_w);
    conv2_kernel<<<6272, 256>>>();          // 2048*49 px x 4 subpos x 4 cg
    fc1_kernel<<<dim3(32, 32), 256>>>();
    fc2_kernel<<<256, 256>>>(out, scale);
}